// round 4
// baseline (speedup 1.0000x reference)
#include <cuda_runtime.h>
#include <math.h>
#include <stdint.h>

// PointLoss_like_GPS — GB300 sm_103a, Round 4
// Rotation identity |dx|+|dy| = max(|dx+dy|,|dx-dy|) rebalances fma->alu pipe.
// Single kernel: last-8-blocks ticket finalize (all blocks resident by
// __launch_bounds__(256,4), so the short spin cannot deadlock).

#define NPTS    4096
#define DIMS    3
#define THREADS 256
#define SPLITS  4
#define RSPLIT  (NPTS / SPLITS)      // 1024 refs per block
#define MAXQ    32768                // 2B*N at B=4
#define FINB    8                    // finalizer blocks

__device__ float        g_dmin[MAXQ * SPLITS];  // layout [q][split] -> float4/query
__device__ float        g_fpart[FINB];
__device__ unsigned int g_ticket1;
__device__ unsigned int g_ticket2;

__device__ __forceinline__ float2 addf32x2(unsigned long long a, unsigned long long b)
{
    float2 r;
    asm("{\n\t"
        ".reg .b64 t;\n\t"
        "add.rn.f32x2 t, %2, %3;\n\t"
        "mov.b64 {%0, %1}, t;\n\t"
        "}"
        : "=f"(r.x), "=f"(r.y) : "l"(a), "l"(b));
    return r;
}

__device__ __forceinline__ unsigned long long bcast2(float v)
{
    unsigned long long r;
    asm("mov.b64 %0, {%1, %1};" : "=l"(r) : "f"(v));
    return r;
}

__global__ void __launch_bounds__(THREADS, 4)
gps_kernel(const float* __restrict__ a1,
           const float* __restrict__ a2,
           const float* __restrict__ alpha_p,
           const float* __restrict__ beta_p,
           float* __restrict__ out,
           int nq, int nblocks, float scale)
{
    __shared__ __align__(16) float shPY[RSPLIT];   // rx + ry
    __shared__ __align__(16) float shMY[RSPLIT];   // rx - ry
    __shared__ __align__(16) float shZ [RSPLIT];   // rz
    __shared__ float red[THREADS / 32];
    __shared__ unsigned int s_ticket;

    const int tid = threadIdx.x;
    const int bx  = blockIdx.x;

    // bx = pair*(16*SPLITS) + qc*SPLITS + sp
    const int sp   = bx & (SPLITS - 1);
    const int qc   = (bx >> 2) & 15;
    const int pair = bx >> 6;
    const int q    = (qc << 8) + tid;
    const int b    = pair >> 1;

    const float* base1 = a1 + (size_t)b * NPTS * DIMS;
    const float* base2 = a2 + (size_t)b * NPTS * DIMS;
    const float* samples = (pair & 1) ? base1 : base2;
    const float* refs    = ((pair & 1) ? base2 : base1) + (size_t)sp * RSPLIT * DIMS;

    const float qx = samples[q * 3 + 0];
    const float qy = samples[q * 3 + 1];
    const float qz = samples[q * 3 + 2];

    const unsigned long long nqpy2 = bcast2(-(qx + qy));
    const unsigned long long nqmy2 = bcast2(-(qx - qy));
    const unsigned long long nqz2  = bcast2(-qz);

    // rotated SoA tile: 4 points per thread
    #pragma unroll
    for (int i = 0; i < RSPLIT / THREADS; i++) {
        const int idx = tid + i * THREADS;
        const float* p = refs + (size_t)idx * 3;
        const float rx = p[0], ry = p[1];
        shPY[idx] = rx + ry;
        shMY[idx] = rx - ry;
        shZ [idx] = p[2];
    }
    __syncthreads();

    float dm0 = 3.402823466e38f, dm1 = dm0, dm2 = dm0, dm3 = dm0;

    const double2* PY = (const double2*)shPY;
    const double2* MY = (const double2*)shMY;
    const double2* ZZ = (const double2*)shZ;

    #pragma unroll 8
    for (int j = 0; j < RSPLIT / 4; j++) {
        const double2 pyv = PY[j], myv = MY[j], zv = ZZ[j];

        const float2 u01 = addf32x2(__double_as_longlong(pyv.x), nqpy2);
        const float2 u23 = addf32x2(__double_as_longlong(pyv.y), nqpy2);
        const float2 v01 = addf32x2(__double_as_longlong(myv.x), nqmy2);
        const float2 v23 = addf32x2(__double_as_longlong(myv.y), nqmy2);
        const float2 z01 = addf32x2(__double_as_longlong(zv.x),  nqz2);
        const float2 z23 = addf32x2(__double_as_longlong(zv.y),  nqz2);

        // |dx|+|dy| = max(|u|,|v|)  -> FMNMX (alu) with abs operand modifiers
        const float s0 = fmaxf(fabsf(u01.x), fabsf(v01.x)) + fabsf(z01.x);
        const float s1 = fmaxf(fabsf(u01.y), fabsf(v01.y)) + fabsf(z01.y);
        const float s2 = fmaxf(fabsf(u23.x), fabsf(v23.x)) + fabsf(z23.x);
        const float s3 = fmaxf(fabsf(u23.y), fabsf(v23.y)) + fabsf(z23.y);

        dm0 = fminf(dm0, s0);
        dm1 = fminf(dm1, s1);
        dm2 = fminf(dm2, s2);
        dm3 = fminf(dm3, s3);
    }

    const float dmin = fminf(fminf(dm0, dm1), fminf(dm2, dm3));
    g_dmin[(size_t)(pair * NPTS + q) * SPLITS + sp] = dmin;

    // ---- ticketed tail: last FINB blocks finalize ----
    __syncthreads();               // all stores in this block issued
    if (tid == 0) {
        __threadfence();
        s_ticket = atomicAdd(&g_ticket1, 1u);
    }
    __syncthreads();
    const unsigned int t = s_ticket;
    if (t < (unsigned)(nblocks - FINB)) return;

    const int rank = (int)t - (nblocks - FINB);

    if (tid == 0) {
        // wait until every block's g_dmin is globally visible
        while (*((volatile unsigned int*)&g_ticket1) < (unsigned)nblocks) { }
    }
    __syncthreads();
    __threadfence();

    // finalize slice: nq/FINB queries per block
    const float alpha = *alpha_p;
    const float beta  = *beta_p;
    const float delta = __powf(alpha, -1.0f / beta);

    const int per_blk = nq / FINB;           // 4096
    const int qbase   = rank * per_blk;
    const float4* dm4 = (const float4*)g_dmin;

    float acc = 0.0f;
    #pragma unroll 4
    for (int i = tid; i < per_blk; i += THREADS) {
        const float4 d = dm4[qbase + i];
        const float dmn = fminf(fminf(d.x, d.y), fminf(d.z, d.w));
        const float sv  = alpha * __powf(dmn, beta) + delta;
        acc += -sv * __expf(-sv);
    }

    #pragma unroll
    for (int o = 16; o > 0; o >>= 1)
        acc += __shfl_down_sync(0xffffffffu, acc, o);
    if ((tid & 31) == 0) red[tid >> 5] = acc;
    __syncthreads();

    if (tid == 0) {
        float v = 0.0f;
        #pragma unroll
        for (int w = 0; w < THREADS / 32; w++) v += red[w];
        g_fpart[rank] = v;
        __threadfence();
        const unsigned int t2 = atomicAdd(&g_ticket2, 1u);
        if (t2 == FINB - 1) {
            float total = 0.0f;
            #pragma unroll
            for (int r = 0; r < FINB; r++)
                total += *((volatile float*)&g_fpart[r]);
            out[0] = total * scale;
            g_ticket1 = 0;       // self-clean for graph replay
            g_ticket2 = 0;
        }
    }
}

extern "C" void kernel_launch(void* const* d_in, const int* in_sizes, int n_in,
                              void* d_out, int out_size)
{
    const float* a1    = (const float*)d_in[0];
    const float* a2    = (const float*)d_in[1];
    const float* alpha = (const float*)d_in[2];
    const float* beta  = (const float*)d_in[3];
    float* out = (float*)d_out;

    const int B  = in_sizes[0] / (NPTS * DIMS);
    const int nq = 2 * B * NPTS;
    const int nblocks = 2 * B * 16 * SPLITS;     // 512 at B=4 (all co-resident)
    const float scale = 50.0f / (float)B;

    gps_kernel<<<nblocks, THREADS>>>(a1, a2, alpha, beta, out, nq, nblocks, scale);
}

// round 5
// speedup vs baseline: 1.0487x; 1.0487x over previous
#include <cuda_runtime.h>
#include <math.h>
#include <stdint.h>

// PointLoss_like_GPS — GB300 sm_103a, Round 5
// R3 inner loop (abs-folded FADDs) + SPLITS=8 + reg-capped occupancy +
// fused ticketed finalize.

#define NPTS    4096
#define DIMS    3
#define THREADS 256
#define SPLITS  8
#define RSPLIT  (NPTS / SPLITS)      // 512 refs per block
#define MAXQ    32768                // 2B*N at B=4
#define FINB    8                    // finalizer blocks

__device__ float        g_dmin[MAXQ * SPLITS];  // layout [q][split]
__device__ float        g_fpart[FINB];
__device__ unsigned int g_ticket1;
__device__ unsigned int g_ticket2;

__device__ __forceinline__ float2 addf32x2(unsigned long long a, unsigned long long b)
{
    float2 r;
    asm("{\n\t"
        ".reg .b64 t;\n\t"
        "add.rn.f32x2 t, %2, %3;\n\t"
        "mov.b64 {%0, %1}, t;\n\t"
        "}"
        : "=f"(r.x), "=f"(r.y) : "l"(a), "l"(b));
    return r;
}

__device__ __forceinline__ unsigned long long bcast2(float v)
{
    unsigned long long r;
    asm("mov.b64 %0, {%1, %1};" : "=l"(r) : "f"(v));
    return r;
}

__global__ void __launch_bounds__(THREADS, 5)
gps_kernel(const float* __restrict__ a1,
           const float* __restrict__ a2,
           const float* __restrict__ alpha_p,
           const float* __restrict__ beta_p,
           float* __restrict__ out,
           int nq, int nblocks, float scale)
{
    __shared__ __align__(16) float shX[RSPLIT];
    __shared__ __align__(16) float shY[RSPLIT];
    __shared__ __align__(16) float shZ[RSPLIT];
    __shared__ float red[THREADS / 32];
    __shared__ unsigned int s_ticket;

    const int tid = threadIdx.x;
    const int bx  = blockIdx.x;

    // bx = pair*(16*SPLITS) + qc*SPLITS + sp
    const int sp   = bx & (SPLITS - 1);
    const int qc   = (bx >> 3) & 15;
    const int pair = bx >> 7;
    const int q    = (qc << 8) + tid;
    const int b    = pair >> 1;

    const float* base1 = a1 + (size_t)b * NPTS * DIMS;
    const float* base2 = a2 + (size_t)b * NPTS * DIMS;
    const float* samples = (pair & 1) ? base1 : base2;
    const float* refs    = ((pair & 1) ? base2 : base1) + (size_t)sp * RSPLIT * DIMS;

    const float qx = samples[q * 3 + 0];
    const float qy = samples[q * 3 + 1];
    const float qz = samples[q * 3 + 2];

    const unsigned long long nqx2 = bcast2(-qx);
    const unsigned long long nqy2 = bcast2(-qy);
    const unsigned long long nqz2 = bcast2(-qz);

    // AoS -> SoA tile (512 points, 6 floats per thread)
    #pragma unroll
    for (int i = 0; i < RSPLIT / THREADS; i++) {
        const int idx = tid + i * THREADS;
        const float* p = refs + (size_t)idx * 3;
        shX[idx] = p[0];
        shY[idx] = p[1];
        shZ[idx] = p[2];
    }
    __syncthreads();

    float dm0 = 3.402823466e38f, dm1 = dm0, dm2 = dm0, dm3 = dm0;

    const double2* X = (const double2*)shX;
    const double2* Y = (const double2*)shY;
    const double2* Z = (const double2*)shZ;

    #pragma unroll 4
    for (int j = 0; j < RSPLIT / 4; j++) {
        const double2 xv = X[j], yv = Y[j], zv = Z[j];

        const float2 dx01 = addf32x2(__double_as_longlong(xv.x), nqx2);
        const float2 dx23 = addf32x2(__double_as_longlong(xv.y), nqx2);
        const float2 dy01 = addf32x2(__double_as_longlong(yv.x), nqy2);
        const float2 dy23 = addf32x2(__double_as_longlong(yv.y), nqy2);
        const float2 dz01 = addf32x2(__double_as_longlong(zv.x), nqz2);
        const float2 dz23 = addf32x2(__double_as_longlong(zv.y), nqz2);

        // abs folds into FADD operand modifiers (proven-fast form)
        const float s0 = (fabsf(dx01.x) + fabsf(dy01.x)) + fabsf(dz01.x);
        const float s1 = (fabsf(dx01.y) + fabsf(dy01.y)) + fabsf(dz01.y);
        const float s2 = (fabsf(dx23.x) + fabsf(dy23.x)) + fabsf(dz23.x);
        const float s3 = (fabsf(dx23.y) + fabsf(dy23.y)) + fabsf(dz23.y);

        dm0 = fminf(dm0, s0);
        dm1 = fminf(dm1, s1);
        dm2 = fminf(dm2, s2);
        dm3 = fminf(dm3, s3);
    }

    const float dmin = fminf(fminf(dm0, dm1), fminf(dm2, dm3));
    g_dmin[(size_t)(pair * NPTS + q) * SPLITS + sp] = dmin;

    // ---- ticketed tail: last FINB blocks finalize ----
    __syncthreads();
    if (tid == 0) {
        __threadfence();
        s_ticket = atomicAdd(&g_ticket1, 1u);
    }
    __syncthreads();
    const unsigned int t = s_ticket;
    if (t < (unsigned)(nblocks - FINB)) return;

    const int rank = (int)t - (nblocks - FINB);

    if (tid == 0) {
        while (*((volatile unsigned int*)&g_ticket1) < (unsigned)nblocks) { }
    }
    __syncthreads();
    __threadfence();

    const float alpha = *alpha_p;
    const float beta  = *beta_p;
    const float delta = __powf(alpha, -1.0f / beta);

    const int per_blk = nq / FINB;           // 4096 queries
    const int qbase   = rank * per_blk;
    const float4* dm4 = (const float4*)g_dmin;   // 2 float4 per query

    float acc = 0.0f;
    #pragma unroll 2
    for (int i = tid; i < per_blk; i += THREADS) {
        const float4 d0 = dm4[(size_t)(qbase + i) * 2 + 0];
        const float4 d1 = dm4[(size_t)(qbase + i) * 2 + 1];
        float dmn = fminf(fminf(fminf(d0.x, d0.y), fminf(d0.z, d0.w)),
                          fminf(fminf(d1.x, d1.y), fminf(d1.z, d1.w)));
        const float sv = alpha * __powf(dmn, beta) + delta;
        acc += -sv * __expf(-sv);
    }

    #pragma unroll
    for (int o = 16; o > 0; o >>= 1)
        acc += __shfl_down_sync(0xffffffffu, acc, o);
    if ((tid & 31) == 0) red[tid >> 5] = acc;
    __syncthreads();

    if (tid == 0) {
        float v = 0.0f;
        #pragma unroll
        for (int w = 0; w < THREADS / 32; w++) v += red[w];
        g_fpart[rank] = v;
        __threadfence();
        const unsigned int t2 = atomicAdd(&g_ticket2, 1u);
        if (t2 == FINB - 1) {
            float total = 0.0f;
            #pragma unroll
            for (int r = 0; r < FINB; r++)
                total += *((volatile float*)&g_fpart[r]);
            out[0] = total * scale;
            g_ticket1 = 0;       // self-clean for graph replay
            g_ticket2 = 0;
        }
    }
}

extern "C" void kernel_launch(void* const* d_in, const int* in_sizes, int n_in,
                              void* d_out, int out_size)
{
    const float* a1    = (const float*)d_in[0];
    const float* a2    = (const float*)d_in[1];
    const float* alpha = (const float*)d_in[2];
    const float* beta  = (const float*)d_in[3];
    float* out = (float*)d_out;

    const int B  = in_sizes[0] / (NPTS * DIMS);
    const int nq = 2 * B * NPTS;
    const int nblocks = 2 * B * 16 * SPLITS;     // 1024 at B=4
    const float scale = 50.0f / (float)B;

    gps_kernel<<<nblocks, THREADS>>>(a1, a2, alpha, beta, out, nq, nblocks, scale);
}